// round 14
// baseline (speedup 1.0000x reference)
#include <cuda_runtime.h>
#include <cstdint>

// ---------------- problem constants ----------------
#define NTOK   32768
#define OUT_FIBER  ((size_t)NTOK * 512)
#define OUT_CONN   (OUT_FIBER + (size_t)NTOK * 1024)
#define OUT_GEN    (OUT_CONN + (size_t)NTOK * 8)

__device__ __forceinline__ void mmabf(float d[4], const uint32_t a[4],
                                      uint32_t b0, uint32_t b1) {
    asm volatile("mma.sync.aligned.m16n8k16.row.col.f32.bf16.bf16.f32 "
                 "{%0,%1,%2,%3},{%4,%5,%6,%7},{%8,%9},{%0,%1,%2,%3};"
                 : "+f"(d[0]), "+f"(d[1]), "+f"(d[2]), "+f"(d[3])
                 : "r"(a[0]), "r"(a[1]), "r"(a[2]), "r"(a[3]), "r"(b0), "r"(b1));
}
__device__ __forceinline__ uint32_t movm(uint32_t a) {
    uint32_t d;
    asm volatile("movmatrix.sync.aligned.m8n8.trans.b16 %0,%1;" : "=r"(d) : "r"(a));
    return d;
}
__device__ __forceinline__ uint32_t cvt2(float even, float odd) {
    uint32_t h; asm("cvt.rn.bf16x2.f32 %0,%1,%2;" : "=r"(h) : "f"(odd), "f"(even));
    return h;
}
__device__ __forceinline__ uint32_t lores(uint32_t h, float e, float o) {
    float he = __uint_as_float(h << 16);
    float ho = __uint_as_float(h & 0xffff0000u);
    return cvt2(e - he, o - ho);
}

__device__ __forceinline__ void zeroD(float (&D)[2][4][4]) {
    #pragma unroll
    for (int m = 0; m < 2; m++)
        #pragma unroll
        for (int n = 0; n < 4; n++)
            #pragma unroll
            for (int k = 0; k < 4; k++) D[m][n][k] = 0.0f;
}

// D accum frags -> bf16x2 hi/lo packs. H[Mt][ct][rr] = 8x8 tile(row-tile 2Mt+rr, col-tile ct)
__device__ __forceinline__ void packHL(const float (&D)[2][4][4],
                                       uint32_t (&H)[2][4][2], uint32_t (&L)[2][4][2]) {
    #pragma unroll
    for (int Mt = 0; Mt < 2; Mt++)
        #pragma unroll
        for (int nt = 0; nt < 4; nt++)
            #pragma unroll
            for (int rr = 0; rr < 2; rr++) {
                float e = D[Mt][nt][2 * rr], o = D[Mt][nt][2 * rr + 1];
                uint32_t h = cvt2(e, o);
                H[Mt][nt][rr] = h;
                L[Mt][nt][rr] = lores(h, e, o);
            }
}

// ---- gramL44: D += M M^T, M tiles M4[rowtile][coltile] (A-layout), hi/lo 3-product ----
__device__ __forceinline__ void gramL44(const uint32_t (&MH4)[4][4],
                                        const uint32_t (&ML4)[4][4],
                                        float (&D)[2][4][4]) {
    #pragma unroll
    for (int Kt = 0; Kt < 2; Kt++)
        #pragma unroll
        for (int Mt = 0; Mt < 2; Mt++) {
            uint32_t aH[4] = {MH4[2*Mt][2*Kt],   MH4[2*Mt+1][2*Kt],
                              MH4[2*Mt][2*Kt+1], MH4[2*Mt+1][2*Kt+1]};
            uint32_t aL[4] = {ML4[2*Mt][2*Kt],   ML4[2*Mt+1][2*Kt],
                              ML4[2*Mt][2*Kt+1], ML4[2*Mt+1][2*Kt+1]};
            #pragma unroll
            for (int nt = 0; nt < 4; nt++) {
                uint32_t b0h = MH4[nt][2*Kt], b1h = MH4[nt][2*Kt+1];
                uint32_t b0l = ML4[nt][2*Kt], b1l = ML4[nt][2*Kt+1];
                mmabf(D[Mt][nt], aH, b0h, b1h);
                mmabf(D[Mt][nt], aH, b0l, b1l);
                mmabf(D[Mt][nt], aL, b0h, b1h);
            }
        }
}

// ---- gramPK: D += M M^T from hi/lo packs (3-product); works for any packed M ----
__device__ __forceinline__ void gramPK(const uint32_t (&H)[2][4][2],
                                       const uint32_t (&L)[2][4][2],
                                       float (&D)[2][4][4]) {
    #pragma unroll
    for (int Kt = 0; Kt < 2; Kt++)
        #pragma unroll
        for (int Mt = 0; Mt < 2; Mt++) {
            uint32_t aH[4] = {H[Mt][2*Kt][0], H[Mt][2*Kt][1],
                              H[Mt][2*Kt+1][0], H[Mt][2*Kt+1][1]};
            uint32_t aL[4] = {L[Mt][2*Kt][0], L[Mt][2*Kt][1],
                              L[Mt][2*Kt+1][0], L[Mt][2*Kt+1][1]};
            #pragma unroll
            for (int nt = 0; nt < 4; nt++) {
                uint32_t b0h = H[nt >> 1][2*Kt][nt & 1], b1h = H[nt >> 1][2*Kt+1][nt & 1];
                uint32_t b0l = L[nt >> 1][2*Kt][nt & 1], b1l = L[nt >> 1][2*Kt+1][nt & 1];
                mmabf(D[Mt][nt], aH, b0h, b1h);
                mmabf(D[Mt][nt], aH, b0l, b1l);
                mmabf(D[Mt][nt], aL, b0h, b1h);
            }
        }
}

// ---- sqH: D += Mh Mh^T from hi pack only (1-product) ----
__device__ __forceinline__ void sqH(const uint32_t (&H)[2][4][2], float (&D)[2][4][4]) {
    #pragma unroll
    for (int Kt = 0; Kt < 2; Kt++)
        #pragma unroll
        for (int Mt = 0; Mt < 2; Mt++) {
            uint32_t aH[4] = {H[Mt][2*Kt][0], H[Mt][2*Kt][1],
                              H[Mt][2*Kt+1][0], H[Mt][2*Kt+1][1]};
            #pragma unroll
            for (int nt = 0; nt < 4; nt++)
                mmabf(D[Mt][nt], aH,
                      H[nt >> 1][2*Kt][nt & 1], H[nt >> 1][2*Kt+1][nt & 1]);
        }
}

__global__ __launch_bounds__(32) void fiber_bundle_kernel(
    const int*   __restrict__ tokens,
    const float* __restrict__ base_w,
    const float* __restrict__ fiber_w,
    const float* __restrict__ conn_w,
    const float* __restrict__ gen,
    float*       __restrict__ out)
{
    const int lane = threadIdx.x;
    const int rw = lane >> 2;              // frag row within 8
    const int cp = (lane & 3) * 2;         // frag col pair base

    const int tokIdx = blockIdx.x;
    const int tok    = tokens[tokIdx];

    // ---- side-copy loads issued early ----
    float4 breg[4];
    {
        const float4* bsrc = (const float4*)(base_w + (size_t)tok * 512);
        #pragma unroll
        for (int j = 0; j < 4; j++) breg[j] = bsrc[lane + 32 * j];
    }
    float cv = 0.0f;
    if (lane < 8) cv = conn_w[(size_t)tok * 8 + lane];
    float4 gv;
    const bool doGen = blockIdx.x < 64;
    if (doGen) gv = ((const float4*)gen)[blockIdx.x * 32 + lane];

    // ---- load X directly in fragment layout (16 LDG.64), split hi/lo ----
    uint32_t XH[4][4], XL[4][4];           // X tiles [rowtile][coltile]
    {
        const float* fx = fiber_w + (size_t)tok * 1024;
        #pragma unroll
        for (int i = 0; i < 4; i++)
            #pragma unroll
            for (int j = 0; j < 4; j++) {
                float2 v = *(const float2*)(fx + (8 * i + rw) * 32 + 8 * j + cp);
                uint32_t h = cvt2(v.x, v.y);
                XH[i][j] = h;
                XL[i][j] = lores(h, v.x, v.y);
            }
    }

    // ---- retire side copies ----
    {
        float4* bdst = (float4*)(out + (size_t)tokIdx * 512);
        #pragma unroll
        for (int j = 0; j < 4; j++) bdst[lane + 32 * j] = breg[j];
    }
    if (lane < 8) out[OUT_CONN + (size_t)tokIdx * 8 + lane] = cv;
    if (doGen) ((float4*)(out + OUT_GEN))[blockIdx.x * 32 + lane] = gv;

    float D[2][4][4];
    uint32_t H[2][4][2], L[2][4][2];

    // ===== (1) B = X X^T  (no transposes needed) =====
    zeroD(D);
    gramL44(XH, XL, D);

    // ===== (2) T = 0.375*(Bq*Bq + 5I - (10/3)B)  (square single-plane) =====
    packHL(D, H, L);                       // B packs (only H used for square)
    #pragma unroll
    for (int Mt = 0; Mt < 2; Mt++)
        #pragma unroll
        for (int nt = 0; nt < 4; nt++) {
            const int c0 = nt * 8 + cp;
            const int r0 = Mt * 16 + rw, r1 = r0 + 8;
            D[Mt][nt][0] = fmaf(D[Mt][nt][0], -3.33333333f, (r0 == c0)     ? 5.0f : 0.0f);
            D[Mt][nt][1] = fmaf(D[Mt][nt][1], -3.33333333f, (r0 == c0 + 1) ? 5.0f : 0.0f);
            D[Mt][nt][2] = fmaf(D[Mt][nt][2], -3.33333333f, (r1 == c0)     ? 5.0f : 0.0f);
            D[Mt][nt][3] = fmaf(D[Mt][nt][3], -3.33333333f, (r1 == c0 + 1) ? 5.0f : 0.0f);
        }
    sqH(H, D);                             // D = Bq^2 + 5I - (10/3)B
    #pragma unroll
    for (int Mt = 0; Mt < 2; Mt++)
        #pragma unroll
        for (int nt = 0; nt < 4; nt++)
            #pragma unroll
            for (int k = 0; k < 4; k++) D[Mt][nt][k] *= 0.375f;
    packHL(D, H, L);                       // T packs (T symmetric)

    // ===== (3) X1 = T * X  (B-frag of X via movmatrix) =====
    {
        uint32_t BXH[4][4], BXL[4][4];     // A-frag of X^T: BX[nt][kt] = movm(X[kt][nt])
        #pragma unroll
        for (int nt = 0; nt < 4; nt++)
            #pragma unroll
            for (int kt = 0; kt < 4; kt++) {
                BXH[nt][kt] = movm(XH[kt][nt]);
                BXL[nt][kt] = movm(XL[kt][nt]);
            }
        zeroD(D);
        #pragma unroll
        for (int Kt = 0; Kt < 2; Kt++)
            #pragma unroll
            for (int Mt = 0; Mt < 2; Mt++) {
                uint32_t aH[4] = {H[Mt][2*Kt][0], H[Mt][2*Kt][1],
                                  H[Mt][2*Kt+1][0], H[Mt][2*Kt+1][1]};
                uint32_t aL[4] = {L[Mt][2*Kt][0], L[Mt][2*Kt][1],
                                  L[Mt][2*Kt+1][0], L[Mt][2*Kt+1][1]};
                #pragma unroll
                for (int nt = 0; nt < 4; nt++) {
                    uint32_t b0h = BXH[nt][2*Kt], b1h = BXH[nt][2*Kt+1];
                    uint32_t b0l = BXL[nt][2*Kt], b1l = BXL[nt][2*Kt+1];
                    mmabf(D[Mt][nt], aH, b0h, b1h);
                    mmabf(D[Mt][nt], aH, b0l, b1l);
                    mmabf(D[Mt][nt], aL, b0h, b1h);
                }
            }
    }

    // ===== (4) G2 = X1 X1^T  (fresh accum; D keeps X1 fp32) =====
    packHL(D, H, L);                       // X1 packs
    float C[2][4][4];
    zeroD(C);
    gramPK(H, L, C);

    // E = 0.5*(I - G2)  (tiny, symmetric) -> single bf16 plane
    uint32_t EH[2][4][2];
    #pragma unroll
    for (int Mt = 0; Mt < 2; Mt++)
        #pragma unroll
        for (int nt = 0; nt < 4; nt++) {
            const int c0 = nt * 8 + cp;
            const int r0 = Mt * 16 + rw, r1 = r0 + 8;
            float e0 = 0.5f * (((r0 == c0)     ? 1.0f : 0.0f) - C[Mt][nt][0]);
            float e1 = 0.5f * (((r0 == c0 + 1) ? 1.0f : 0.0f) - C[Mt][nt][1]);
            float e2 = 0.5f * (((r1 == c0)     ? 1.0f : 0.0f) - C[Mt][nt][2]);
            float e3 = 0.5f * (((r1 == c0 + 1) ? 1.0f : 0.0f) - C[Mt][nt][3]);
            EH[Mt][nt][0] = cvt2(e0, e1);
            EH[Mt][nt][1] = cvt2(e2, e3);
        }

    // ===== (5) Xf = X1 + E * X1h  (accumulate into D holding X1 fp32) =====
    {
        uint32_t BH1[4][4];                // A-frag of X1^T: BH1[nt][k] = movm(X1 tile(k, nt))
        #pragma unroll
        for (int nt = 0; nt < 4; nt++)
            #pragma unroll
            for (int k = 0; k < 4; k++)
                BH1[nt][k] = movm(H[k >> 1][nt][k & 1]);
        #pragma unroll
        for (int Kt = 0; Kt < 2; Kt++)
            #pragma unroll
            for (int Mt = 0; Mt < 2; Mt++) {
                uint32_t aH[4] = {EH[Mt][2*Kt][0], EH[Mt][2*Kt][1],
                                  EH[Mt][2*Kt+1][0], EH[Mt][2*Kt+1][1]};
                #pragma unroll
                for (int nt = 0; nt < 4; nt++)
                    mmabf(D[Mt][nt], aH, BH1[nt][2*Kt], BH1[nt][2*Kt+1]);
            }
    }

    // ---- write fiber output ----
    {
        float* fdst = out + OUT_FIBER + (size_t)tokIdx * 1024;
        #pragma unroll
        for (int Mt = 0; Mt < 2; Mt++)
            #pragma unroll
            for (int nt = 0; nt < 4; nt++) {
                const int c0 = nt * 8 + cp;
                const int r0 = Mt * 16 + rw;
                *(float2*)(fdst + r0 * 32 + c0)       = make_float2(D[Mt][nt][0], D[Mt][nt][1]);
                *(float2*)(fdst + (r0 + 8) * 32 + c0) = make_float2(D[Mt][nt][2], D[Mt][nt][3]);
            }
    }
}

extern "C" void kernel_launch(void* const* d_in, const int* in_sizes, int n_in,
                              void* d_out, int out_size)
{
    const int*   tokens  = (const int*)  d_in[0];
    const float* base_w  = (const float*)d_in[1];
    const float* fiber_w = (const float*)d_in[2];
    const float* conn_w  = (const float*)d_in[3];
    const float* gen     = (const float*)d_in[4];
    float* out = (float*)d_out;

    dim3 grid(NTOK);       // 32768 one-warp blocks, 1 matrix each
    dim3 block(32);
    fiber_bundle_kernel<<<grid, block>>>(tokens, base_w, fiber_w, conn_w, gen, out);
}

// round 15
// speedup vs baseline: 1.1078x; 1.1078x over previous
#include <cuda_runtime.h>
#include <cstdint>

// ---------------- problem constants ----------------
#define NTOK   32768
#define OUT_FIBER  ((size_t)NTOK * 512)
#define OUT_CONN   (OUT_FIBER + (size_t)NTOK * 1024)
#define OUT_GEN    (OUT_CONN + (size_t)NTOK * 8)
#define WPB    4                           // warps (independent matrices) per block

__device__ __forceinline__ void mmabf(float d[4], const uint32_t a[4],
                                      uint32_t b0, uint32_t b1) {
    asm volatile("mma.sync.aligned.m16n8k16.row.col.f32.bf16.bf16.f32 "
                 "{%0,%1,%2,%3},{%4,%5,%6,%7},{%8,%9},{%0,%1,%2,%3};"
                 : "+f"(d[0]), "+f"(d[1]), "+f"(d[2]), "+f"(d[3])
                 : "r"(a[0]), "r"(a[1]), "r"(a[2]), "r"(a[3]), "r"(b0), "r"(b1));
}
__device__ __forceinline__ uint32_t movm(uint32_t a) {
    uint32_t d;
    asm volatile("movmatrix.sync.aligned.m8n8.trans.b16 %0,%1;" : "=r"(d) : "r"(a));
    return d;
}
__device__ __forceinline__ uint32_t cvt2(float even, float odd) {
    uint32_t h; asm("cvt.rn.bf16x2.f32 %0,%1,%2;" : "=r"(h) : "f"(odd), "f"(even));
    return h;
}
__device__ __forceinline__ uint32_t lores(uint32_t h, float e, float o) {
    float he = __uint_as_float(h << 16);
    float ho = __uint_as_float(h & 0xffff0000u);
    return cvt2(e - he, o - ho);
}

__device__ __forceinline__ void zeroD(float (&D)[2][4][4]) {
    #pragma unroll
    for (int m = 0; m < 2; m++)
        #pragma unroll
        for (int n = 0; n < 4; n++)
            #pragma unroll
            for (int k = 0; k < 4; k++) D[m][n][k] = 0.0f;
}

// D accum frags -> bf16x2 hi/lo packs. H[Mt][ct][rr] = 8x8 tile(row-tile 2Mt+rr, col-tile ct)
__device__ __forceinline__ void packHL(const float (&D)[2][4][4],
                                       uint32_t (&H)[2][4][2], uint32_t (&L)[2][4][2]) {
    #pragma unroll
    for (int Mt = 0; Mt < 2; Mt++)
        #pragma unroll
        for (int nt = 0; nt < 4; nt++)
            #pragma unroll
            for (int rr = 0; rr < 2; rr++) {
                float e = D[Mt][nt][2 * rr], o = D[Mt][nt][2 * rr + 1];
                uint32_t h = cvt2(e, o);
                H[Mt][nt][rr] = h;
                L[Mt][nt][rr] = lores(h, e, o);
            }
}

// ---- gramL44: D += M M^T, M tiles (A-layout), hi/lo 3-product ----
__device__ __forceinline__ void gramL44(const uint32_t (&MH4)[4][4],
                                        const uint32_t (&ML4)[4][4],
                                        float (&D)[2][4][4]) {
    #pragma unroll
    for (int Kt = 0; Kt < 2; Kt++)
        #pragma unroll
        for (int Mt = 0; Mt < 2; Mt++) {
            uint32_t aH[4] = {MH4[2*Mt][2*Kt],   MH4[2*Mt+1][2*Kt],
                              MH4[2*Mt][2*Kt+1], MH4[2*Mt+1][2*Kt+1]};
            uint32_t aL[4] = {ML4[2*Mt][2*Kt],   ML4[2*Mt+1][2*Kt],
                              ML4[2*Mt][2*Kt+1], ML4[2*Mt+1][2*Kt+1]};
            #pragma unroll
            for (int nt = 0; nt < 4; nt++) {
                uint32_t b0h = MH4[nt][2*Kt], b1h = MH4[nt][2*Kt+1];
                uint32_t b0l = ML4[nt][2*Kt], b1l = ML4[nt][2*Kt+1];
                mmabf(D[Mt][nt], aH, b0h, b1h);
                mmabf(D[Mt][nt], aH, b0l, b1l);
                mmabf(D[Mt][nt], aL, b0h, b1h);
            }
        }
}

// ---- gramPK: D += M M^T from hi/lo packs (3-product) ----
__device__ __forceinline__ void gramPK(const uint32_t (&H)[2][4][2],
                                       const uint32_t (&L)[2][4][2],
                                       float (&D)[2][4][4]) {
    #pragma unroll
    for (int Kt = 0; Kt < 2; Kt++)
        #pragma unroll
        for (int Mt = 0; Mt < 2; Mt++) {
            uint32_t aH[4] = {H[Mt][2*Kt][0], H[Mt][2*Kt][1],
                              H[Mt][2*Kt+1][0], H[Mt][2*Kt+1][1]};
            uint32_t aL[4] = {L[Mt][2*Kt][0], L[Mt][2*Kt][1],
                              L[Mt][2*Kt+1][0], L[Mt][2*Kt+1][1]};
            #pragma unroll
            for (int nt = 0; nt < 4; nt++) {
                uint32_t b0h = H[nt >> 1][2*Kt][nt & 1], b1h = H[nt >> 1][2*Kt+1][nt & 1];
                uint32_t b0l = L[nt >> 1][2*Kt][nt & 1], b1l = L[nt >> 1][2*Kt+1][nt & 1];
                mmabf(D[Mt][nt], aH, b0h, b1h);
                mmabf(D[Mt][nt], aH, b0l, b1l);
                mmabf(D[Mt][nt], aL, b0h, b1h);
            }
        }
}

// ---- sqH: D += Mh Mh^T from hi pack only (1-product) ----
__device__ __forceinline__ void sqH(const uint32_t (&H)[2][4][2], float (&D)[2][4][4]) {
    #pragma unroll
    for (int Kt = 0; Kt < 2; Kt++)
        #pragma unroll
        for (int Mt = 0; Mt < 2; Mt++) {
            uint32_t aH[4] = {H[Mt][2*Kt][0], H[Mt][2*Kt][1],
                              H[Mt][2*Kt+1][0], H[Mt][2*Kt+1][1]};
            #pragma unroll
            for (int nt = 0; nt < 4; nt++)
                mmabf(D[Mt][nt], aH,
                      H[nt >> 1][2*Kt][nt & 1], H[nt >> 1][2*Kt+1][nt & 1]);
        }
}

__global__ __launch_bounds__(32 * WPB) void fiber_bundle_kernel(
    const int*   __restrict__ tokens,
    const float* __restrict__ base_w,
    const float* __restrict__ fiber_w,
    const float* __restrict__ conn_w,
    const float* __restrict__ gen,
    float*       __restrict__ out)
{
    const int wid  = threadIdx.x >> 5;
    const int lane = threadIdx.x & 31;
    const int rw = lane >> 2;              // frag row within 8
    const int cp = (lane & 3) * 2;         // frag col pair base

    const int tokIdx = blockIdx.x * WPB + wid;
    const int tok    = tokens[tokIdx];

    // ---- side-copy loads issued early ----
    float4 breg[4];
    {
        const float4* bsrc = (const float4*)(base_w + (size_t)tok * 512);
        #pragma unroll
        for (int j = 0; j < 4; j++) breg[j] = bsrc[lane + 32 * j];
    }
    float cv = 0.0f;
    if (lane < 8) cv = conn_w[(size_t)tok * 8 + lane];
    float4 gv;
    const bool doGen = blockIdx.x < 16;    // 16 blocks x 128 threads = 2048 float4
    if (doGen) gv = ((const float4*)gen)[blockIdx.x * 128 + threadIdx.x];

    // ---- load X directly in fragment layout (16 LDG.64), split hi/lo ----
    uint32_t XH[4][4], XL[4][4];
    {
        const float* fx = fiber_w + (size_t)tok * 1024;
        #pragma unroll
        for (int i = 0; i < 4; i++)
            #pragma unroll
            for (int j = 0; j < 4; j++) {
                float2 v = *(const float2*)(fx + (8 * i + rw) * 32 + 8 * j + cp);
                uint32_t h = cvt2(v.x, v.y);
                XH[i][j] = h;
                XL[i][j] = lores(h, v.x, v.y);
            }
    }

    // ---- retire side copies ----
    {
        float4* bdst = (float4*)(out + (size_t)tokIdx * 512);
        #pragma unroll
        for (int j = 0; j < 4; j++) bdst[lane + 32 * j] = breg[j];
    }
    if (lane < 8) out[OUT_CONN + (size_t)tokIdx * 8 + lane] = cv;
    if (doGen) ((float4*)(out + OUT_GEN))[blockIdx.x * 128 + threadIdx.x] = gv;

    float D[2][4][4];
    uint32_t H[2][4][2], L[2][4][2];

    // ===== (1) B = X X^T  (no transposes needed) =====
    zeroD(D);
    gramL44(XH, XL, D);

    // ===== (2) T = 0.375*(Bq*Bq + 5I - (10/3)B)  (square single-plane) =====
    packHL(D, H, L);                       // B packs
    #pragma unroll
    for (int Mt = 0; Mt < 2; Mt++)
        #pragma unroll
        for (int nt = 0; nt < 4; nt++) {
            const int c0 = nt * 8 + cp;
            const int r0 = Mt * 16 + rw, r1 = r0 + 8;
            D[Mt][nt][0] = fmaf(D[Mt][nt][0], -3.33333333f, (r0 == c0)     ? 5.0f : 0.0f);
            D[Mt][nt][1] = fmaf(D[Mt][nt][1], -3.33333333f, (r0 == c0 + 1) ? 5.0f : 0.0f);
            D[Mt][nt][2] = fmaf(D[Mt][nt][2], -3.33333333f, (r1 == c0)     ? 5.0f : 0.0f);
            D[Mt][nt][3] = fmaf(D[Mt][nt][3], -3.33333333f, (r1 == c0 + 1) ? 5.0f : 0.0f);
        }
    sqH(H, D);
    #pragma unroll
    for (int Mt = 0; Mt < 2; Mt++)
        #pragma unroll
        for (int nt = 0; nt < 4; nt++)
            #pragma unroll
            for (int k = 0; k < 4; k++) D[Mt][nt][k] *= 0.375f;
    packHL(D, H, L);                       // T packs (T symmetric)

    // ===== (3) X1 = T * X  (B-frag of X via movmatrix) =====
    {
        uint32_t BXH[4][4], BXL[4][4];
        #pragma unroll
        for (int nt = 0; nt < 4; nt++)
            #pragma unroll
            for (int kt = 0; kt < 4; kt++) {
                BXH[nt][kt] = movm(XH[kt][nt]);
                BXL[nt][kt] = movm(XL[kt][nt]);
            }
        zeroD(D);
        #pragma unroll
        for (int Kt = 0; Kt < 2; Kt++)
            #pragma unroll
            for (int Mt = 0; Mt < 2; Mt++) {
                uint32_t aH[4] = {H[Mt][2*Kt][0], H[Mt][2*Kt][1],
                                  H[Mt][2*Kt+1][0], H[Mt][2*Kt+1][1]};
                uint32_t aL[4] = {L[Mt][2*Kt][0], L[Mt][2*Kt][1],
                                  L[Mt][2*Kt+1][0], L[Mt][2*Kt+1][1]};
                #pragma unroll
                for (int nt = 0; nt < 4; nt++) {
                    uint32_t b0h = BXH[nt][2*Kt], b1h = BXH[nt][2*Kt+1];
                    uint32_t b0l = BXL[nt][2*Kt], b1l = BXL[nt][2*Kt+1];
                    mmabf(D[Mt][nt], aH, b0h, b1h);
                    mmabf(D[Mt][nt], aH, b0l, b1l);
                    mmabf(D[Mt][nt], aL, b0h, b1h);
                }
            }
    }

    // ===== (4) G2 = X1 X1^T  (fresh accum; D keeps X1 fp32) =====
    packHL(D, H, L);                       // X1 packs
    float C[2][4][4];
    zeroD(C);
    gramPK(H, L, C);

    // E = 0.5*(I - G2)  -> single bf16 plane
    uint32_t EH[2][4][2];
    #pragma unroll
    for (int Mt = 0; Mt < 2; Mt++)
        #pragma unroll
        for (int nt = 0; nt < 4; nt++) {
            const int c0 = nt * 8 + cp;
            const int r0 = Mt * 16 + rw, r1 = r0 + 8;
            float e0 = 0.5f * (((r0 == c0)     ? 1.0f : 0.0f) - C[Mt][nt][0]);
            float e1 = 0.5f * (((r0 == c0 + 1) ? 1.0f : 0.0f) - C[Mt][nt][1]);
            float e2 = 0.5f * (((r1 == c0)     ? 1.0f : 0.0f) - C[Mt][nt][2]);
            float e3 = 0.5f * (((r1 == c0 + 1) ? 1.0f : 0.0f) - C[Mt][nt][3]);
            EH[Mt][nt][0] = cvt2(e0, e1);
            EH[Mt][nt][1] = cvt2(e2, e3);
        }

    // ===== (5) Xf = X1 + E * X1h  (accumulate into D) =====
    {
        uint32_t BH1[4][4];
        #pragma unroll
        for (int nt = 0; nt < 4; nt++)
            #pragma unroll
            for (int k = 0; k < 4; k++)
                BH1[nt][k] = movm(H[k >> 1][nt][k & 1]);
        #pragma unroll
        for (int Kt = 0; Kt < 2; Kt++)
            #pragma unroll
            for (int Mt = 0; Mt < 2; Mt++) {
                uint32_t aH[4] = {EH[Mt][2*Kt][0], EH[Mt][2*Kt][1],
                                  EH[Mt][2*Kt+1][0], EH[Mt][2*Kt+1][1]};
                #pragma unroll
                for (int nt = 0; nt < 4; nt++)
                    mmabf(D[Mt][nt], aH, BH1[nt][2*Kt], BH1[nt][2*Kt+1]);
            }
    }

    // ---- write fiber output ----
    {
        float* fdst = out + OUT_FIBER + (size_t)tokIdx * 1024;
        #pragma unroll
        for (int Mt = 0; Mt < 2; Mt++)
            #pragma unroll
            for (int nt = 0; nt < 4; nt++) {
                const int c0 = nt * 8 + cp;
                const int r0 = Mt * 16 + rw;
                *(float2*)(fdst + r0 * 32 + c0)       = make_float2(D[Mt][nt][0], D[Mt][nt][1]);
                *(float2*)(fdst + (r0 + 8) * 32 + c0) = make_float2(D[Mt][nt][2], D[Mt][nt][3]);
            }
    }
}

extern "C" void kernel_launch(void* const* d_in, const int* in_sizes, int n_in,
                              void* d_out, int out_size)
{
    const int*   tokens  = (const int*)  d_in[0];
    const float* base_w  = (const float*)d_in[1];
    const float* fiber_w = (const float*)d_in[2];
    const float* conn_w  = (const float*)d_in[3];
    const float* gen     = (const float*)d_in[4];
    float* out = (float*)d_out;

    dim3 grid(NTOK / WPB);   // 8192 blocks, 4 independent warps each
    dim3 block(32 * WPB);
    fiber_bundle_kernel<<<grid, block>>>(tokens, base_w, fiber_w, conn_w, gen, out);
}